// round 1
// baseline (speedup 1.0000x reference)
#include <cuda_runtime.h>
#include <math.h>

#define BATCH 64
#define NPART 512
#define SPLIT 4
#define BLK   128
#define EPT   (NPART / BLK)   // elements per thread in load phase = 4

// Scratch (no allocation allowed) — partial sums + per-batch metadata.
// g_part[b][s][0..3] = sum_xy per class (1..4), [4..7] = sum_yx per class.
__device__ float g_part[BATCH][SPLIT][8];
// g_meta[b]: [0..3]=cx, [4..7]=cy, [8..11]=sum||t|| per class, [12..15]=sum||r|| per class,
//            [16]=cnt0 (out_pid==0), [17]=sum||r|| over out_pid==0
__device__ float g_meta[BATCH][18];

__global__ __launch_bounds__(BLK)
void chamfer_main(const float4* __restrict__ target,
                  const float4* __restrict__ reco,
                  const int*    __restrict__ in_pid,
                  const int*    __restrict__ out_pid)
{
    __shared__ float4 sT[NPART];           // targets compacted by class
    __shared__ float4 sR[NPART];           // recos compacted by class
    __shared__ int    cntX[5], cntY[5];
    __shared__ int    offX[6], offY[6];
    __shared__ int    curX[5], curY[5];
    __shared__ float  sNT[5], sNR[5];      // per-class norm sums
    __shared__ float  accA[5], accB[5];    // per-class partial chamfer sums

    const int b   = blockIdx.x / SPLIT;
    const int s   = blockIdx.x % SPLIT;
    const int tid = threadIdx.x;

    if (tid < 5) {
        cntX[tid] = 0; cntY[tid] = 0;
        sNT[tid] = 0.f; sNR[tid] = 0.f;
        accA[tid] = 0.f; accB[tid] = 0.f;
    }
    __syncthreads();

    const float4* Tb  = target  + b * NPART;
    const float4* Rb  = reco    + b * NPART;
    const int*    IPb = in_pid  + b * NPART;
    const int*    OPb = out_pid + b * NPART;

    // ---- Load phase: values kept in registers across barriers; count bins ----
    float4 tv[EPT], rv[EPT];
    int    tp[EPT], rp[EPT];
#pragma unroll
    for (int e = 0; e < EPT; e++) {
        const int i = tid + e * BLK;
        tv[e] = Tb[i];
        rv[e] = Rb[i];
        tp[e] = IPb[i];
        rp[e] = OPb[i];
        atomicAdd(&cntX[tp[e]], 1);
        atomicAdd(&cntY[rp[e]], 1);
        const float4 t = tv[e], r = rv[e];
        atomicAdd(&sNT[tp[e]], sqrtf(t.x*t.x + t.y*t.y + t.z*t.z + t.w*t.w));
        atomicAdd(&sNR[rp[e]], sqrtf(r.x*r.x + r.y*r.y + r.z*r.z + r.w*r.w));
    }
    __syncthreads();

    if (tid == 0) {
        int ax = 0, ay = 0;
        for (int q = 0; q < 5; q++) {
            offX[q] = ax; curX[q] = ax; ax += cntX[q];
            offY[q] = ay; curY[q] = ay; ay += cntY[q];
        }
        offX[5] = ax; offY[5] = ay;
    }
    __syncthreads();

    // ---- Scatter into class-grouped compacted arrays ----
#pragma unroll
    for (int e = 0; e < EPT; e++) {
        sT[atomicAdd(&curX[tp[e]], 1)] = tv[e];
        sR[atomicAdd(&curY[rp[e]], 1)] = rv[e];
    }
    __syncthreads();

    // ---- Main work: one min per particle (classes 1..4 only) ----
    const int nA = NPART - offX[1];   // target-side items
    const int nB = NPART - offY[1];   // reco-side items

    for (int m = s * BLK + tid; m < nA + nB; m += SPLIT * BLK) {
        const bool passA = (m < nA);
        int k = passA ? (offX[1] + m) : (offY[1] + (m - nA));
        const int* off_self  = passA ? offX : offY;
        const int* off_other = passA ? offY : offX;

        int q = 1;
        while (k >= off_self[q + 1]) q++;

        const int jb = off_other[q], je = off_other[q + 1];
        if (jb == je) continue;      // opposite side empty: handled via only_x/only_y

        const float4  x     = passA ? sT[k] : sR[k];
        const float4* other = passA ? sR : sT;

        float md = INFINITY;
#pragma unroll 4
        for (int j = jb; j < je; j++) {
            const float4 y = other[j];
            const float dx = x.x - y.x;
            const float dy = x.y - y.y;
            const float dz = x.z - y.z;
            const float dw = x.w - y.w;
            const float d2 = dx*dx + dy*dy + dz*dz + dw*dw;
            md = fminf(md, d2);
        }
        atomicAdd(passA ? &accA[q] : &accB[q], sqrtf(md));
    }
    __syncthreads();

    if (tid < 4) {
        g_part[b][s][tid]     = accA[tid + 1];
        g_part[b][s][4 + tid] = accB[tid + 1];
    }
    if (s == 0 && tid == 0) {
        for (int q = 1; q < 5; q++) {
            g_meta[b][q - 1]  = (float)cntX[q];
            g_meta[b][3 + q]  = (float)cntY[q];
            g_meta[b][7 + q]  = sNT[q];
            g_meta[b][11 + q] = sNR[q];
        }
        g_meta[b][16] = (float)cntY[0];
        g_meta[b][17] = sNR[0];
    }
}

__global__ void chamfer_reduce(float* __restrict__ out, int out_size)
{
    __shared__ float nz[BATCH], zz[BATCH];
    const int b = threadIdx.x;
    if (b < BATCH) {
        float nzsum = 0.f;
#pragma unroll
        for (int q = 0; q < 4; q++) {
            const float cx = g_meta[b][q];
            const float cy = g_meta[b][4 + q];
            float sxy = 0.f, syx = 0.f;
#pragma unroll
            for (int s = 0; s < SPLIT; s++) {
                sxy += g_part[b][s][q];
                syx += g_part[b][s][4 + q];
            }
            float per;
            if (cy == 0.f)      per = g_meta[b][8 + q]  / fmaxf(1.f, cx);  // only_x
            else if (cx == 0.f) per = g_meta[b][12 + q] / fmaxf(1.f, cy);  // only_y
            else                per = 0.5f * (sxy / fmaxf(1.f, cy) + syx / fmaxf(1.f, cx));
            nzsum += per;
        }
        nz[b] = nzsum;
        zz[b] = g_meta[b][17] / fmaxf(1.f, g_meta[b][16]);
    }
    __syncthreads();
    if (b == 0) {
        float a = 0.f, c = 0.f;
        for (int i = 0; i < BATCH; i++) { a += nz[i]; c += zz[i]; }
        out[0] = a / (float)BATCH;
        if (out_size > 1) out[1] = c / (float)BATCH;
    }
}

extern "C" void kernel_launch(void* const* d_in, const int* in_sizes, int n_in,
                              void* d_out, int out_size)
{
    const float4* target = (const float4*)d_in[0];
    const float4* reco   = (const float4*)d_in[1];
    const int*    ipid   = (const int*)d_in[2];
    const int*    opid   = (const int*)d_in[3];
    float*        out    = (float*)d_out;
    (void)in_sizes; (void)n_in;

    chamfer_main<<<BATCH * SPLIT, BLK>>>(target, reco, ipid, opid);
    chamfer_reduce<<<1, BATCH>>>(out, out_size);
}

// round 2
// speedup vs baseline: 1.2829x; 1.2829x over previous
#include <cuda_runtime.h>
#include <math.h>

#define BATCH 64
#define NPART 512
#define SPLIT 2
#define BLK   256
#define EPT   (NPART / BLK)      // 2 elements per thread in load phase
#define NW    (BLK / 32)         // 8 warps
#define NGRP  (NW * EPT)         // 16 (warp, e) groups per side
#define GRID  (BATCH * SPLIT)    // 128 CTAs

// Scratch (no allocation allowed).
// g_part[b][s][0..3] = sum_xy per class (1..4), [4..7] = sum_yx per class.
__device__ float g_part[BATCH][SPLIT][8];
// g_meta[b]: [0..3]=cx(1..4), [4..7]=cy(1..4), [8..11]=sum||t|| per class,
//            [12..15]=sum||r|| per class, [16]=cnt0, [17]=sum||r|| class 0
__device__ float g_meta[BATCH][18];
__device__ int   g_ticket;       // zero-initialized; last CTA resets it

__global__ __launch_bounds__(BLK)
void chamfer_fused(const float4* __restrict__ target,
                   const float4* __restrict__ reco,
                   const int*    __restrict__ in_pid,
                   const int*    __restrict__ out_pid,
                   float* __restrict__ out, int out_size)
{
    __shared__ float4 sT[NPART], sR[NPART];      // class-compacted particles
    __shared__ float  sNT[NPART], sNR[NPART];    // compacted norms
    __shared__ int    bX[NGRP][5], bY[NGRP][5];  // group counts -> group prefixes
    __shared__ int    totX[5], totY[5];
    __shared__ int    offX[6], offY[6];
    __shared__ float  accA[5], accB[5];
    __shared__ int    is_last;
    __shared__ float  nzb[BATCH], zzb[BATCH];

    const int b    = blockIdx.x / SPLIT;
    const int s    = blockIdx.x % SPLIT;
    const int tid  = threadIdx.x;
    const int w    = tid >> 5;
    const int lane = tid & 31;
    const unsigned lt = (1u << lane) - 1u;

    if (tid < 5) { accA[tid] = 0.f; accB[tid] = 0.f; }
    if (tid < NGRP * 5) { (&bX[0][0])[tid] = 0; (&bY[0][0])[tid] = 0; }
    __syncthreads();

    const float4* Tb  = target  + b * NPART;
    const float4* Rb  = reco    + b * NPART;
    const int*    IPb = in_pid  + b * NPART;
    const int*    OPb = out_pid + b * NPART;

    // ---- Load + atomic-free binning via match_any + lane rank ----
    float4 tv[EPT], rv[EPT];
    int    tp[EPT], rp[EPT], rkX[EPT], rkY[EPT];
#pragma unroll
    for (int e = 0; e < EPT; e++) {
        const int i = e * BLK + tid;
        tv[e] = Tb[i]; rv[e] = Rb[i];
        tp[e] = IPb[i]; rp[e] = OPb[i];
        const unsigned mX = __match_any_sync(0xffffffffu, tp[e]);
        const unsigned mY = __match_any_sync(0xffffffffu, rp[e]);
        rkX[e] = __popc(mX & lt);
        rkY[e] = __popc(mY & lt);
        const int g = w * EPT + e;
        if (rkX[e] == 0) bX[g][tp[e]] = __popc(mX);
        if (rkY[e] == 0) bY[g][rp[e]] = __popc(mY);
    }
    __syncthreads();

    // ---- Exclusive prefix over the 16 groups, per class (10 threads) ----
    if (tid < 10) {
        const int side = tid / 5, q = tid % 5;
        int (*bb)[5] = side ? bY : bX;
        int run = 0;
        for (int g = 0; g < NGRP; g++) { const int c = bb[g][q]; bb[g][q] = run; run += c; }
        if (side) totY[q] = run; else totX[q] = run;
    }
    __syncthreads();
    if (tid == 0) { int a = 0; for (int q = 0; q < 5; q++) { offX[q] = a; a += totX[q]; } offX[5] = a; }
    if (tid == 1) { int a = 0; for (int q = 0; q < 5; q++) { offY[q] = a; a += totY[q]; } offY[5] = a; }
    __syncthreads();

    // ---- Deterministic scatter (no atomics), storing norms alongside ----
#pragma unroll
    for (int e = 0; e < EPT; e++) {
        const int g  = w * EPT + e;
        const int ix = offX[tp[e]] + bX[g][tp[e]] + rkX[e];
        const int iy = offY[rp[e]] + bY[g][rp[e]] + rkY[e];
        const float4 t = tv[e], r = rv[e];
        sT[ix] = t;
        sR[iy] = r;
        sNT[ix] = sqrtf(t.x*t.x + t.y*t.y + t.z*t.z + t.w*t.w);
        sNR[iy] = sqrtf(r.x*r.x + r.y*r.y + r.z*r.z + r.w*r.w);
    }
    __syncthreads();

    // ---- Per-batch metadata (counts + class-contiguous norm segment sums) ----
    if (s == 0) {
        if (tid < 4) {
            g_meta[b][tid]     = (float)(offX[tid + 2] - offX[tid + 1]);   // cx q=1..4
            g_meta[b][4 + tid] = (float)(offY[tid + 2] - offY[tid + 1]);   // cy q=1..4
        }
        if (tid == 4) g_meta[b][16] = (float)(offY[1] - offY[0]);          // cnt0
        for (int seg = w; seg < 9; seg += NW) {
            int lo, hi; const float* arr;
            if (seg < 4) { arr = sNT; lo = offX[seg + 1]; hi = offX[seg + 2]; }
            else         { arr = sNR; lo = offY[seg - 4]; hi = offY[seg - 3]; }
            float sum = 0.f;
            for (int j = lo + lane; j < hi; j += 32) sum += arr[j];
#pragma unroll
            for (int o = 16; o; o >>= 1) sum += __shfl_down_sync(0xffffffffu, sum, o);
            if (lane == 0) {
                if (seg < 4)       g_meta[b][8 + seg]        = sum;  // sNT class seg+1
                else if (seg == 4) g_meta[b][17]             = sum;  // sNR class 0
                else               g_meta[b][12 + (seg - 5)] = sum;  // sNR class 1..4
            }
        }
    }

    // ---- Main work: one min per particle (classes 1..4 only) ----
    const int nA = NPART - offX[1];
    const int nB = NPART - offY[1];

    for (int m = s * BLK + tid; m < nA + nB; m += SPLIT * BLK) {
        const bool passA = (m < nA);
        int k = passA ? (offX[1] + m) : (offY[1] + (m - nA));
        const int* off_self  = passA ? offX : offY;
        const int* off_other = passA ? offY : offX;

        int q = 1;
        while (k >= off_self[q + 1]) q++;

        const int jb = off_other[q], je = off_other[q + 1];
        if (jb == je) continue;   // opposite side empty: handled via only_x/only_y

        const float4  x     = passA ? sT[k] : sR[k];
        const float4* other = passA ? sR : sT;

        float md = INFINITY;
#pragma unroll 4
        for (int j = jb; j < je; j++) {
            const float4 y = other[j];
            const float dx = x.x - y.x;
            const float dy = x.y - y.y;
            const float dz = x.z - y.z;
            const float dw = x.w - y.w;
            const float d2 = dx*dx + dy*dy + dz*dz + dw*dw;
            md = fminf(md, d2);
        }
        atomicAdd(passA ? &accA[q] : &accB[q], sqrtf(md));
    }
    __syncthreads();

    if (tid < 4) {
        g_part[b][s][tid]     = accA[tid + 1];
        g_part[b][s][4 + tid] = accB[tid + 1];
    }

    // ---- Last-CTA fused reduction ----
    __threadfence();
    __syncthreads();                       // ensure g_part writes issued by all threads' POV
    if (tid == 0) {
        const int t = atomicAdd(&g_ticket, 1);
        is_last = (t == GRID - 1);
    }
    __syncthreads();
    if (!is_last) return;

    __threadfence();                       // acquire: make all CTAs' writes visible
    if (tid < BATCH) {
        const int bb = tid;
        float nzsum = 0.f;
#pragma unroll
        for (int q = 0; q < 4; q++) {
            const float cx = g_meta[bb][q];
            const float cy = g_meta[bb][4 + q];
            float sxy = 0.f, syx = 0.f;
#pragma unroll
            for (int ss = 0; ss < SPLIT; ss++) {
                sxy += g_part[bb][ss][q];
                syx += g_part[bb][ss][4 + q];
            }
            float per;
            if (cy == 0.f)      per = g_meta[bb][8 + q]  / fmaxf(1.f, cx);
            else if (cx == 0.f) per = g_meta[bb][12 + q] / fmaxf(1.f, cy);
            else                per = 0.5f * (sxy / fmaxf(1.f, cy) + syx / fmaxf(1.f, cx));
            nzsum += per;
        }
        nzb[tid] = nzsum;
        zzb[tid] = g_meta[bb][17] / fmaxf(1.f, g_meta[bb][16]);
    }
    __syncthreads();
    if (tid == 0) {
        float a = 0.f, c = 0.f;
        for (int i = 0; i < BATCH; i++) { a += nzb[i]; c += zzb[i]; }
        out[0] = a / (float)BATCH;
        if (out_size > 1) out[1] = c / (float)BATCH;
        g_ticket = 0;                      // reset for next graph replay
    }
}

extern "C" void kernel_launch(void* const* d_in, const int* in_sizes, int n_in,
                              void* d_out, int out_size)
{
    const float4* target = (const float4*)d_in[0];
    const float4* reco   = (const float4*)d_in[1];
    const int*    ipid   = (const int*)d_in[2];
    const int*    opid   = (const int*)d_in[3];
    float*        out    = (float*)d_out;
    (void)in_sizes; (void)n_in;

    chamfer_fused<<<GRID, BLK>>>(target, reco, ipid, opid, out, out_size);
}

// round 3
// speedup vs baseline: 1.5017x; 1.1706x over previous
#include <cuda_runtime.h>
#include <math.h>

#define BATCH 64
#define NPART 512
#define SPLIT 4
#define BLK   256
#define EPT   (NPART / BLK)      // 2 elements per thread in load phase
#define NW    (BLK / 32)         // 8 warps
#define NGRP  (NW * EPT)         // 16 (warp, e) groups per side
#define GRID  (BATCH * SPLIT)    // 256 CTAs

// Scratch (no allocation allowed).
// g_part[b][s][0..3] = sum_xy per class (1..4), [4..7] = sum_yx per class.
__device__ float g_part[BATCH][SPLIT][8];
// g_meta[b]: [0..3]=cx(1..4), [4..7]=cy(1..4), [8..11]=sum||t|| per class,
//            [12..15]=sum||r|| per class, [16]=cnt0, [17]=sum||r|| class 0
__device__ float g_meta[BATCH][18];
__device__ int   g_ticket;       // zero-initialized; last CTA resets it

__global__ __launch_bounds__(BLK)
void chamfer_fused(const float4* __restrict__ target,
                   const float4* __restrict__ reco,
                   const int*    __restrict__ in_pid,
                   const int*    __restrict__ out_pid,
                   float* __restrict__ out, int out_size)
{
    __shared__ float4 sT[NPART], sR[NPART];      // class-compacted particles
    __shared__ float  sQT[NPART], sQR[NPART];    // 0.5*|p|^2 (compacted)
    __shared__ float  sNT[NPART], sNR[NPART];    // |p| (compacted, for metadata)
    __shared__ int    bX[NGRP][5], bY[NGRP][5];  // group counts -> group prefixes
    __shared__ int    totX[5], totY[5];
    __shared__ int    offX[6], offY[6];
    __shared__ float  accA[5], accB[5];
    __shared__ int    is_last;
    __shared__ float  nzb[BATCH], zzb[BATCH];

    const int b    = blockIdx.x / SPLIT;
    const int s    = blockIdx.x % SPLIT;
    const int tid  = threadIdx.x;
    const int w    = tid >> 5;
    const int lane = tid & 31;
    const unsigned lt = (1u << lane) - 1u;

    if (tid < 5) { accA[tid] = 0.f; accB[tid] = 0.f; }
    if (tid < NGRP * 5) { (&bX[0][0])[tid] = 0; (&bY[0][0])[tid] = 0; }
    __syncthreads();

    const float4* Tb  = target  + b * NPART;
    const float4* Rb  = reco    + b * NPART;
    const int*    IPb = in_pid  + b * NPART;
    const int*    OPb = out_pid + b * NPART;

    // ---- Load + atomic-free binning via match_any + lane rank ----
    float4 tv[EPT], rv[EPT];
    int    tp[EPT], rp[EPT], rkX[EPT], rkY[EPT];
#pragma unroll
    for (int e = 0; e < EPT; e++) {
        const int i = e * BLK + tid;
        tv[e] = Tb[i]; rv[e] = Rb[i];
        tp[e] = IPb[i]; rp[e] = OPb[i];
        const unsigned mX = __match_any_sync(0xffffffffu, tp[e]);
        const unsigned mY = __match_any_sync(0xffffffffu, rp[e]);
        rkX[e] = __popc(mX & lt);
        rkY[e] = __popc(mY & lt);
        const int g = w * EPT + e;
        if (rkX[e] == 0) bX[g][tp[e]] = __popc(mX);
        if (rkY[e] == 0) bY[g][rp[e]] = __popc(mY);
    }
    __syncthreads();

    // ---- Exclusive prefix over the 16 groups, per class: register-resident ----
    if (tid < 10) {
        const int side = tid / 5, q = tid % 5;
        int (*bb)[5] = side ? bY : bX;
        int v[NGRP];
#pragma unroll
        for (int g = 0; g < NGRP; g++) v[g] = bb[g][q];   // pipelined LDS
        int run = 0;
#pragma unroll
        for (int g = 0; g < NGRP; g++) { const int c = v[g]; bb[g][q] = run; run += c; }
        if (side) totY[q] = run; else totX[q] = run;
    }
    __syncthreads();
    if (tid == 0) { int a = 0; for (int q = 0; q < 5; q++) { offX[q] = a; a += totX[q]; } offX[5] = a; }
    if (tid == 1) { int a = 0; for (int q = 0; q < 5; q++) { offY[q] = a; a += totY[q]; } offY[5] = a; }
    __syncthreads();

    // ---- Deterministic scatter (no atomics): particle, half-sq-norm, norm ----
#pragma unroll
    for (int e = 0; e < EPT; e++) {
        const int g  = w * EPT + e;
        const int ix = offX[tp[e]] + bX[g][tp[e]] + rkX[e];
        const int iy = offY[rp[e]] + bY[g][rp[e]] + rkY[e];
        const float4 t = tv[e], r = rv[e];
        const float tq = t.x*t.x + t.y*t.y + t.z*t.z + t.w*t.w;
        const float rq = r.x*r.x + r.y*r.y + r.z*r.z + r.w*r.w;
        sT[ix] = t;  sQT[ix] = 0.5f * tq;  sNT[ix] = sqrtf(tq);
        sR[iy] = r;  sQR[iy] = 0.5f * rq;  sNR[iy] = sqrtf(rq);
    }
    __syncthreads();

    // ---- Per-batch metadata (counts + class-contiguous norm segment sums) ----
    if (s == 0) {
        if (tid < 4) {
            g_meta[b][tid]     = (float)(offX[tid + 2] - offX[tid + 1]);   // cx q=1..4
            g_meta[b][4 + tid] = (float)(offY[tid + 2] - offY[tid + 1]);   // cy q=1..4
        }
        if (tid == 4) g_meta[b][16] = (float)(offY[1] - offY[0]);          // cnt0
        for (int seg = w; seg < 9; seg += NW) {
            int lo, hi; const float* arr;
            if (seg < 4) { arr = sNT; lo = offX[seg + 1]; hi = offX[seg + 2]; }
            else         { arr = sNR; lo = offY[seg - 4]; hi = offY[seg - 3]; }
            float sum = 0.f;
            for (int j = lo + lane; j < hi; j += 32) sum += arr[j];
#pragma unroll
            for (int o = 16; o; o >>= 1) sum += __shfl_down_sync(0xffffffffu, sum, o);
            if (lane == 0) {
                if (seg < 4)       g_meta[b][8 + seg]        = sum;  // sNT class seg+1
                else if (seg == 4) g_meta[b][17]             = sum;  // sNR class 0
                else               g_meta[b][12 + (seg - 5)] = sum;  // sNR class 1..4
            }
        }
    }

    // ---- Main work: one min per particle (classes 1..4 only) ----
    // min_j |x-y_j|^2 = |x|^2 + 2*min_j(h_j - x.y_j),  h_j = 0.5|y_j|^2
    const int nA = NPART - offX[1];
    const int nB = NPART - offY[1];

    for (int m = s * BLK + tid; m < nA + nB; m += SPLIT * BLK) {
        const bool passA = (m < nA);
        int k = passA ? (offX[1] + m) : (offY[1] + (m - nA));
        const int* off_self  = passA ? offX : offY;
        const int* off_other = passA ? offY : offX;

        int q = 1;
        while (k >= off_self[q + 1]) q++;

        const int jb = off_other[q], je = off_other[q + 1];
        if (jb == je) continue;   // opposite side empty: handled via only_x/only_y

        const float4  x     = passA ? sT[k]  : sR[k];
        const float   xsq   = 2.f * (passA ? sQT[k] : sQR[k]);
        const float4* other = passA ? sR  : sT;
        const float*  hoth  = passA ? sQR : sQT;

        const float nx = -x.x, ny = -x.y, nz = -x.z, nw = -x.w;

        float ms0 = INFINITY, ms1 = INFINITY;
        int j = jb;
        if ((je - jb) & 1) {
            const float4 y = other[j];
            ms0 = fmaf(nx, y.x, fmaf(ny, y.y, fmaf(nz, y.z, fmaf(nw, y.w, hoth[j]))));
            j++;
        }
#pragma unroll 4
        for (; j < je; j += 2) {
            const float4 y0 = other[j];
            const float4 y1 = other[j + 1];
            const float s0 = fmaf(nx, y0.x, fmaf(ny, y0.y, fmaf(nz, y0.z, fmaf(nw, y0.w, hoth[j]))));
            const float s1 = fmaf(nx, y1.x, fmaf(ny, y1.y, fmaf(nz, y1.z, fmaf(nw, y1.w, hoth[j + 1]))));
            ms0 = fminf(ms0, s0);
            ms1 = fminf(ms1, s1);
        }
        const float ms = fminf(ms0, ms1);
        const float d2 = fmaxf(fmaf(2.f, ms, xsq), 0.f);
        atomicAdd(passA ? &accA[q] : &accB[q], sqrtf(d2));
    }
    __syncthreads();

    if (tid < 4) {
        g_part[b][s][tid]     = accA[tid + 1];
        g_part[b][s][4 + tid] = accB[tid + 1];
    }

    // ---- Last-CTA fused reduction ----
    __threadfence();
    __syncthreads();
    if (tid == 0) {
        const int t = atomicAdd(&g_ticket, 1);
        is_last = (t == GRID - 1);
    }
    __syncthreads();
    if (!is_last) return;

    __threadfence();                       // acquire: make all CTAs' writes visible
    if (tid < BATCH) {
        const int bb = tid;
        float nzsum = 0.f;
#pragma unroll
        for (int q = 0; q < 4; q++) {
            const float cx = g_meta[bb][q];
            const float cy = g_meta[bb][4 + q];
            float sxy = 0.f, syx = 0.f;
#pragma unroll
            for (int ss = 0; ss < SPLIT; ss++) {
                sxy += g_part[bb][ss][q];
                syx += g_part[bb][ss][4 + q];
            }
            float per;
            if (cy == 0.f)      per = g_meta[bb][8 + q]  / fmaxf(1.f, cx);
            else if (cx == 0.f) per = g_meta[bb][12 + q] / fmaxf(1.f, cy);
            else                per = 0.5f * (sxy / fmaxf(1.f, cy) + syx / fmaxf(1.f, cx));
            nzsum += per;
        }
        nzb[tid] = nzsum;
        zzb[tid] = g_meta[bb][17] / fmaxf(1.f, g_meta[bb][16]);
    }
    __syncthreads();
    if (tid == 0) {
        float a = 0.f, c = 0.f;
        for (int i = 0; i < BATCH; i++) { a += nzb[i]; c += zzb[i]; }
        out[0] = a / (float)BATCH;
        if (out_size > 1) out[1] = c / (float)BATCH;
        g_ticket = 0;                      // reset for next graph replay
    }
}

extern "C" void kernel_launch(void* const* d_in, const int* in_sizes, int n_in,
                              void* d_out, int out_size)
{
    const float4* target = (const float4*)d_in[0];
    const float4* reco   = (const float4*)d_in[1];
    const int*    ipid   = (const int*)d_in[2];
    const int*    opid   = (const int*)d_in[3];
    float*        out    = (float*)d_out;
    (void)in_sizes; (void)n_in;

    chamfer_fused<<<GRID, BLK>>>(target, reco, ipid, opid, out, out_size);
}